// round 1
// baseline (speedup 1.0000x reference)
#include <cuda_runtime.h>

// TemporalViewModel GRU: T=24 steps, N=65536 sequences (B*X*Y), F=32 -> H=32,
// gates 3H=96 (torch order r,z,n), then h_final @ W (32x16) -> out (N,16).
//
// Strategy: one thread per sequence. Weights in shared memory (broadcast reads).
// All dot products run on packed f32x2 FMAs (SASS FFMA2) with the K dimension
// packed in pairs; weight rows are contiguous so ld.shared.v2.b64 delivers two
// packed operands per load (1 LDS128 : 4 FFMA2). fp32 accumulation throughout.

namespace {
constexpr int T_STEPS = 24;
constexpr int NSEQ    = 65536;   // B*X*Y = 16*64*64
constexpr int S       = 16;
constexpr int M       = 8;
constexpr int C       = 8;
constexpr int F       = 32;      // S+M+C
constexpr int H       = 32;
constexpr int G       = 96;      // 3H
}

typedef unsigned long long u64;

__device__ __forceinline__ u64 pk2(float lo, float hi) {
    u64 d; asm("mov.b64 %0, {%1, %2};" : "=l"(d) : "f"(lo), "f"(hi)); return d;
}
__device__ __forceinline__ float hsum2(u64 a) {
    float lo, hi;
    asm("mov.b64 {%0, %1}, %2;" : "=f"(lo), "=f"(hi) : "l"(a));
    return lo + hi;
}
__device__ __forceinline__ float lo2(u64 a) {
    float lo, hi;
    asm("mov.b64 {%0, %1}, %2;" : "=f"(lo), "=f"(hi) : "l"(a));
    return lo;
}
__device__ __forceinline__ float hi2(u64 a) {
    float lo, hi;
    asm("mov.b64 {%0, %1}, %2;" : "=f"(lo), "=f"(hi) : "l"(a));
    return hi;
}
// d = a*b + c on both packed fp32 lanes (SASS: FFMA2). Only reachable via PTX.
__device__ __forceinline__ u64 fma2(u64 a, u64 b, u64 c) {
    u64 d; asm("fma.rn.f32x2 %0, %1, %2, %3;" : "=l"(d) : "l"(a), "l"(b), "l"(c));
    return d;
}
__device__ __forceinline__ float sigm(float x) {
    return __fdividef(1.f, 1.f + __expf(-x));
}
__device__ __forceinline__ float tanh_fast(float x) {
    // tanh(x) = 2*sigmoid(2x) - 1 ; __expf rel err ~2e-7, saturates correctly.
    return __fdividef(2.f, 1.f + __expf(-2.f * x)) - 1.f;
}

__global__ void __launch_bounds__(64, 7)
gru_fused_kernel(const float* __restrict__ spatial,
                 const float* __restrict__ met,
                 const float* __restrict__ ctx,
                 const float* __restrict__ Wih,   // (96, 32)
                 const float* __restrict__ Whh,   // (96, 32)
                 const float* __restrict__ bih,   // (96,)
                 const float* __restrict__ bhh,   // (96,)
                 const float* __restrict__ Wout,  // (32, 16)
                 float* __restrict__ out)         // (N, 16)
{
    __shared__ __align__(16) float sWih[G * F];
    __shared__ __align__(16) float sWhh[G * H];
    __shared__ float sBih[G];
    __shared__ float sBhh[G];
    __shared__ __align__(16) float sWo[H * S];

    for (int i = threadIdx.x; i < G * F; i += blockDim.x) sWih[i] = Wih[i];
    for (int i = threadIdx.x; i < G * H; i += blockDim.x) sWhh[i] = Whh[i];
    for (int i = threadIdx.x; i < G; i += blockDim.x) { sBih[i] = bih[i]; sBhh[i] = bhh[i]; }
    for (int i = threadIdx.x; i < H * S; i += blockDim.x) sWo[i] = Wout[i];
    __syncthreads();

    const int n = blockIdx.x * blockDim.x + threadIdx.x;

    u64 h2[H / 2];                 // hidden state, K-packed pairs
    #pragma unroll
    for (int i = 0; i < H / 2; i++) h2[i] = 0ull;
    float hnew[H];                 // scalar view of the freshly computed h

    #pragma unroll 1
    for (int t = 0; t < T_STEPS; t++) {
        // ---- load x = concat(spatial, met, ctx), pack K pairs ----
        u64 x2[F / 2];
        {
            const float4* sp = reinterpret_cast<const float4*>(spatial + ((size_t)t * NSEQ + n) * S);
            const float4* mp = reinterpret_cast<const float4*>(met     + ((size_t)t * NSEQ + n) * M);
            const float4* cp = reinterpret_cast<const float4*>(ctx     + ((size_t)t * NSEQ + n) * C);
            float4 v;
            #pragma unroll
            for (int q = 0; q < 4; q++) {
                v = sp[q];
                x2[2 * q]     = pk2(v.x, v.y);
                x2[2 * q + 1] = pk2(v.z, v.w);
            }
            #pragma unroll
            for (int q = 0; q < 2; q++) {
                v = mp[q];
                x2[8 + 2 * q] = pk2(v.x, v.y);
                x2[9 + 2 * q] = pk2(v.z, v.w);
            }
            #pragma unroll
            for (int q = 0; q < 2; q++) {
                v = cp[q];
                x2[12 + 2 * q] = pk2(v.x, v.y);
                x2[13 + 2 * q] = pk2(v.z, v.w);
            }
        }

        // ---- per hidden unit j: 6 dot products of length 32, packed x2 ----
        #pragma unroll 2
        for (int j = 0; j < H; j++) {
            const ulonglong2* wr = reinterpret_cast<const ulonglong2*>(sWih + j * F);
            const ulonglong2* wz = reinterpret_cast<const ulonglong2*>(sWih + (j + H) * F);
            const ulonglong2* wn = reinterpret_cast<const ulonglong2*>(sWih + (j + 2 * H) * F);
            const ulonglong2* ur = reinterpret_cast<const ulonglong2*>(sWhh + j * H);
            const ulonglong2* uz = reinterpret_cast<const ulonglong2*>(sWhh + (j + H) * H);
            const ulonglong2* un = reinterpret_cast<const ulonglong2*>(sWhh + (j + 2 * H) * H);

            u64 ar = 0, az = 0, an = 0, br = 0, bz = 0, bn = 0;
            #pragma unroll
            for (int k = 0; k < F / 4; k++) {
                ulonglong2 w;
                w = wr[k]; ar = fma2(w.x, x2[2 * k], ar); ar = fma2(w.y, x2[2 * k + 1], ar);
                w = wz[k]; az = fma2(w.x, x2[2 * k], az); az = fma2(w.y, x2[2 * k + 1], az);
                w = wn[k]; an = fma2(w.x, x2[2 * k], an); an = fma2(w.y, x2[2 * k + 1], an);
                w = ur[k]; br = fma2(w.x, h2[2 * k], br); br = fma2(w.y, h2[2 * k + 1], br);
                w = uz[k]; bz = fma2(w.x, h2[2 * k], bz); bz = fma2(w.y, h2[2 * k + 1], bz);
                w = un[k]; bn = fma2(w.x, h2[2 * k], bn); bn = fma2(w.y, h2[2 * k + 1], bn);
            }

            float gr  = hsum2(ar) + hsum2(br) + sBih[j]         + sBhh[j];
            float gz  = hsum2(az) + hsum2(bz) + sBih[j + H]     + sBhh[j + H];
            float gxn = hsum2(an) + sBih[j + 2 * H];
            float ghn = hsum2(bn) + sBhh[j + 2 * H];

            float r  = sigm(gr);
            float z  = sigm(gz);
            float nn = tanh_fast(fmaf(r, ghn, gxn));
            float hold = (j & 1) ? hi2(h2[j >> 1]) : lo2(h2[j >> 1]);
            hnew[j] = fmaf(z, hold - nn, nn);   // (1-z)*n + z*h
        }

        // repack new hidden state
        #pragma unroll
        for (int i = 0; i < H / 2; i++) h2[i] = pk2(hnew[2 * i], hnew[2 * i + 1]);
    }

    // ---- output projection: out[n, :] = h_final @ W (32x16) ----
    float acc[S];
    #pragma unroll
    for (int s = 0; s < S; s++) acc[s] = 0.f;
    #pragma unroll
    for (int k = 0; k < H; k++) {
        float hk = hnew[k];
        #pragma unroll
        for (int s = 0; s < S; s++) acc[s] = fmaf(hk, sWo[k * S + s], acc[s]);
    }
    float4* op = reinterpret_cast<float4*>(out + (size_t)n * S);
    #pragma unroll
    for (int q = 0; q < 4; q++)
        op[q] = make_float4(acc[4 * q], acc[4 * q + 1], acc[4 * q + 2], acc[4 * q + 3]);
}

extern "C" void kernel_launch(void* const* d_in, const int* in_sizes, int n_in,
                              void* d_out, int out_size) {
    (void)in_sizes; (void)n_in; (void)out_size;
    const float* spatial = (const float*)d_in[0];
    const float* met     = (const float*)d_in[1];
    const float* ctx     = (const float*)d_in[2];
    const float* Wih     = (const float*)d_in[3];
    const float* Whh     = (const float*)d_in[4];
    const float* bih     = (const float*)d_in[5];
    const float* bhh     = (const float*)d_in[6];
    const float* Wo      = (const float*)d_in[7];
    float* out           = (float*)d_out;

    gru_fused_kernel<<<NSEQ / 64, 64>>>(spatial, met, ctx, Wih, Whh, bih, bhh, Wo, out);
}

// round 2
// speedup vs baseline: 1.1680x; 1.1680x over previous
#include <cuda_runtime.h>

// TemporalViewModel GRU: T=24, N=65536 seqs, F=32 -> H=32, gates 3H=96 (r,z,n),
// then h_final @ W (32x16).
//
// R2: two sequences per thread. Each shared-memory weight load (LDS.128,
// warp-broadcast) now feeds 4 packed f32x2 FMAs (2 per sequence), halving the
// L1tex/smem wavefront pressure that bound R1 (L1=82%, fma=41.5%).

namespace {
constexpr int T_STEPS = 24;
constexpr int NSEQ    = 65536;   // B*X*Y
constexpr int HALF    = NSEQ / 2;
constexpr int S       = 16;
constexpr int M       = 8;
constexpr int C       = 8;
constexpr int F       = 32;
constexpr int H       = 32;
constexpr int G       = 96;
}

typedef unsigned long long u64;

__device__ __forceinline__ u64 pk2(float lo, float hi) {
    u64 d; asm("mov.b64 %0, {%1, %2};" : "=l"(d) : "f"(lo), "f"(hi)); return d;
}
__device__ __forceinline__ float hsum2(u64 a) {
    float lo, hi;
    asm("mov.b64 {%0, %1}, %2;" : "=f"(lo), "=f"(hi) : "l"(a));
    return lo + hi;
}
__device__ __forceinline__ float lane2(u64 a, int hi_lane) {
    float lo, hi;
    asm("mov.b64 {%0, %1}, %2;" : "=f"(lo), "=f"(hi) : "l"(a));
    return hi_lane ? hi : lo;
}
// packed fp32x2 fma / add (SASS FFMA2 / FADD2-ish) — only reachable via PTX.
__device__ __forceinline__ u64 fma2(u64 a, u64 b, u64 c) {
    u64 d; asm("fma.rn.f32x2 %0, %1, %2, %3;" : "=l"(d) : "l"(a), "l"(b), "l"(c));
    return d;
}
__device__ __forceinline__ u64 add2(u64 a, u64 b) {
    u64 d; asm("add.rn.f32x2 %0, %1, %2;" : "=l"(d) : "l"(a), "l"(b));
    return d;
}
__device__ __forceinline__ float sigm(float x) {
    return __fdividef(1.f, 1.f + __expf(-x));
}
__device__ __forceinline__ float tanh_fast(float x) {
    return __fdividef(2.f, 1.f + __expf(-2.f * x)) - 1.f;
}

// load x = concat(spatial[16], met[8], ctx[8]) for sequence n at step t, packed in K-pairs
__device__ __forceinline__ void load_x(const float* __restrict__ spatial,
                                       const float* __restrict__ met,
                                       const float* __restrict__ ctx,
                                       int t, int n, u64* x2) {
    const float4* sp = reinterpret_cast<const float4*>(spatial + ((size_t)t * NSEQ + n) * S);
    const float4* mp = reinterpret_cast<const float4*>(met     + ((size_t)t * NSEQ + n) * M);
    const float4* cp = reinterpret_cast<const float4*>(ctx     + ((size_t)t * NSEQ + n) * C);
    float4 v;
    #pragma unroll
    for (int q = 0; q < 4; q++) {
        v = sp[q];
        x2[2 * q]     = pk2(v.x, v.y);
        x2[2 * q + 1] = pk2(v.z, v.w);
    }
    #pragma unroll
    for (int q = 0; q < 2; q++) {
        v = mp[q];
        x2[8 + 2 * q] = pk2(v.x, v.y);
        x2[9 + 2 * q] = pk2(v.z, v.w);
    }
    #pragma unroll
    for (int q = 0; q < 2; q++) {
        v = cp[q];
        x2[12 + 2 * q] = pk2(v.x, v.y);
        x2[13 + 2 * q] = pk2(v.z, v.w);
    }
}

__global__ void __launch_bounds__(64, 4)
gru_fused2_kernel(const float* __restrict__ spatial,
                  const float* __restrict__ met,
                  const float* __restrict__ ctx,
                  const float* __restrict__ Wih,   // (96, 32)
                  const float* __restrict__ Whh,   // (96, 32)
                  const float* __restrict__ bih,   // (96,)
                  const float* __restrict__ bhh,   // (96,)
                  const float* __restrict__ Wout,  // (32, 16)
                  float* __restrict__ out)         // (N, 16)
{
    __shared__ __align__(16) float sWih[G * F];
    __shared__ __align__(16) float sWhh[G * H];
    __shared__ float sBr[H];    // bih[j] + bhh[j]
    __shared__ float sBz[H];    // bih[H+j] + bhh[H+j]
    __shared__ float sBnx[H];   // bih[2H+j]
    __shared__ float sBnh[H];   // bhh[2H+j]
    __shared__ __align__(16) float sWo[H * S];

    for (int i = threadIdx.x; i < G * F; i += blockDim.x) sWih[i] = Wih[i];
    for (int i = threadIdx.x; i < G * H; i += blockDim.x) sWhh[i] = Whh[i];
    for (int i = threadIdx.x; i < H; i += blockDim.x) {
        sBr[i]  = bih[i] + bhh[i];
        sBz[i]  = bih[H + i] + bhh[H + i];
        sBnx[i] = bih[2 * H + i];
        sBnh[i] = bhh[2 * H + i];
    }
    for (int i = threadIdx.x; i < H * S; i += blockDim.x) sWo[i] = Wout[i];
    __syncthreads();

    const int n0 = blockIdx.x * blockDim.x + threadIdx.x;   // 0..32767
    const int n1 = n0 + HALF;                               // 32768..65535

    u64 ha2[H / 2], hb2[H / 2];
    #pragma unroll
    for (int i = 0; i < H / 2; i++) { ha2[i] = 0ull; hb2[i] = 0ull; }
    float hna[H], hnb[H];

    #pragma unroll 1
    for (int t = 0; t < T_STEPS; t++) {
        u64 xa2[F / 2], xb2[F / 2];
        load_x(spatial, met, ctx, t, n0, xa2);
        load_x(spatial, met, ctx, t, n1, xb2);

        #pragma unroll 1
        for (int j = 0; j < H; j++) {
            const ulonglong2* wr = reinterpret_cast<const ulonglong2*>(sWih + j * F);
            const ulonglong2* wz = reinterpret_cast<const ulonglong2*>(sWih + (j + H) * F);
            const ulonglong2* wn = reinterpret_cast<const ulonglong2*>(sWih + (j + 2 * H) * F);
            const ulonglong2* ur = reinterpret_cast<const ulonglong2*>(sWhh + j * H);
            const ulonglong2* uz = reinterpret_cast<const ulonglong2*>(sWhh + (j + H) * H);
            const ulonglong2* un = reinterpret_cast<const ulonglong2*>(sWhh + (j + 2 * H) * H);

            u64 ara = 0, aza = 0, ana = 0, bra = 0, bza = 0, bna = 0;   // seq A
            u64 arb = 0, azb = 0, anb = 0, brb = 0, bzb = 0, bnb = 0;   // seq B
            #pragma unroll
            for (int k = 0; k < F / 4; k++) {
                const u64 xaL = xa2[2 * k], xaH = xa2[2 * k + 1];
                const u64 xbL = xb2[2 * k], xbH = xb2[2 * k + 1];
                const u64 haL = ha2[2 * k], haH = ha2[2 * k + 1];
                const u64 hbL = hb2[2 * k], hbH = hb2[2 * k + 1];
                ulonglong2 w;
                w = wr[k];
                ara = fma2(w.x, xaL, ara); ara = fma2(w.y, xaH, ara);
                arb = fma2(w.x, xbL, arb); arb = fma2(w.y, xbH, arb);
                w = wz[k];
                aza = fma2(w.x, xaL, aza); aza = fma2(w.y, xaH, aza);
                azb = fma2(w.x, xbL, azb); azb = fma2(w.y, xbH, azb);
                w = wn[k];
                ana = fma2(w.x, xaL, ana); ana = fma2(w.y, xaH, ana);
                anb = fma2(w.x, xbL, anb); anb = fma2(w.y, xbH, anb);
                w = ur[k];
                bra = fma2(w.x, haL, bra); bra = fma2(w.y, haH, bra);
                brb = fma2(w.x, hbL, brb); brb = fma2(w.y, hbH, brb);
                w = uz[k];
                bza = fma2(w.x, haL, bza); bza = fma2(w.y, haH, bza);
                bzb = fma2(w.x, hbL, bzb); bzb = fma2(w.y, hbH, bzb);
                w = un[k];
                bna = fma2(w.x, haL, bna); bna = fma2(w.y, haH, bna);
                bnb = fma2(w.x, hbL, bnb); bnb = fma2(w.y, hbH, bnb);
            }

            const float br_ = sBr[j], bz_ = sBz[j], bnx_ = sBnx[j], bnh_ = sBnh[j];

            // seq A
            {
                float gr  = hsum2(add2(ara, bra)) + br_;
                float gz  = hsum2(add2(aza, bza)) + bz_;
                float gxn = hsum2(ana) + bnx_;
                float ghn = hsum2(bna) + bnh_;
                float r   = sigm(gr);
                float z   = sigm(gz);
                float nn  = tanh_fast(fmaf(r, ghn, gxn));
                float hold = lane2(ha2[j >> 1], j & 1);
                hna[j] = fmaf(z, hold - nn, nn);
            }
            // seq B
            {
                float gr  = hsum2(add2(arb, brb)) + br_;
                float gz  = hsum2(add2(azb, bzb)) + bz_;
                float gxn = hsum2(anb) + bnx_;
                float ghn = hsum2(bnb) + bnh_;
                float r   = sigm(gr);
                float z   = sigm(gz);
                float nn  = tanh_fast(fmaf(r, ghn, gxn));
                float hold = lane2(hb2[j >> 1], j & 1);
                hnb[j] = fmaf(z, hold - nn, nn);
            }
        }

        #pragma unroll
        for (int i = 0; i < H / 2; i++) {
            ha2[i] = pk2(hna[2 * i], hna[2 * i + 1]);
            hb2[i] = pk2(hnb[2 * i], hnb[2 * i + 1]);
        }
    }

    // ---- output projection: out = h_final @ W (32x16), both sequences ----
    float acca[S], accb[S];
    #pragma unroll
    for (int s = 0; s < S; s++) { acca[s] = 0.f; accb[s] = 0.f; }
    #pragma unroll
    for (int k = 0; k < H; k++) {
        const float hka = hna[k], hkb = hnb[k];
        #pragma unroll
        for (int s = 0; s < S; s++) {
            acca[s] = fmaf(hka, sWo[k * S + s], acca[s]);
            accb[s] = fmaf(hkb, sWo[k * S + s], accb[s]);
        }
    }
    float4* opa = reinterpret_cast<float4*>(out + (size_t)n0 * S);
    float4* opb = reinterpret_cast<float4*>(out + (size_t)n1 * S);
    #pragma unroll
    for (int q = 0; q < 4; q++) {
        opa[q] = make_float4(acca[4 * q], acca[4 * q + 1], acca[4 * q + 2], acca[4 * q + 3]);
        opb[q] = make_float4(accb[4 * q], accb[4 * q + 1], accb[4 * q + 2], accb[4 * q + 3]);
    }
}

extern "C" void kernel_launch(void* const* d_in, const int* in_sizes, int n_in,
                              void* d_out, int out_size) {
    (void)in_sizes; (void)n_in; (void)out_size;
    const float* spatial = (const float*)d_in[0];
    const float* met     = (const float*)d_in[1];
    const float* ctx     = (const float*)d_in[2];
    const float* Wih     = (const float*)d_in[3];
    const float* Whh     = (const float*)d_in[4];
    const float* bih     = (const float*)d_in[5];
    const float* bhh     = (const float*)d_in[6];
    const float* Wo      = (const float*)d_in[7];
    float* out           = (float*)d_out;

    gru_fused2_kernel<<<HALF / 64, 64>>>(spatial, met, ctx, Wih, Whh, bih, bhh, Wo, out);
}